// round 2
// baseline (speedup 1.0000x reference)
#include <cuda_runtime.h>

// Problem constants (match reference)
#define MASK_P   0.15f
#define MASK_LEN 8
#define B_DIM    64
#define H_DIM    512
#define W_DIM    256
#define C_DIM    4

#define BSPLIT   4                     // batch chunks (grid.y)
#define B_PER_T  (B_DIM / BSPLIT)      // 16 batches streamed per thread

// x:         [B, H, W, C] f32
// time_rand: [B, MASK_LEN, W, C] f32
// freq_rand: [B, H, MASK_LEN, C] f32
// time_starts/freq_starts: [B] i32
// out = x * mask[None]; mask is an AND over all 64 batches of "not masked".

__global__ __launch_bounds__(256)
void masking_kernel(const float4* __restrict__ x,
                    const float4* __restrict__ time_rand,   // [B,8,W] of float4
                    const float4* __restrict__ freq_rand,   // [B,H,8] of float4
                    const int*    __restrict__ time_starts,
                    const int*    __restrict__ freq_starts,
                    float4*       __restrict__ out)
{
    __shared__ int s_ts[B_DIM];
    __shared__ int s_fs[B_DIM];

    if (threadIdx.x < B_DIM) {
        s_ts[threadIdx.x] = time_starts[threadIdx.x];
        s_fs[threadIdx.x] = freq_starts[threadIdx.x];
    }
    __syncthreads();

    const int tid = blockIdx.x * blockDim.x + threadIdx.x;   // one per (h, w)
    const int w = tid & (W_DIM - 1);
    const int h = tid >> 8;                                  // W_DIM = 256

    // ---- Phase 1: build the 4-channel mask for this (h, w) pixel.
    // The mask is batch-independent (AND over ALL 64 batches), so every
    // batch-chunk recomputes it; the rand loads are tiny and L2-resident.
    float4 m = make_float4(1.f, 1.f, 1.f, 1.f);

    #pragma unroll 4
    for (int b = 0; b < B_DIM; ++b) {
        int lt = h - s_ts[b];
        if ((unsigned)lt < (unsigned)MASK_LEN) {
            float4 tr = __ldg(&time_rand[(b * MASK_LEN + lt) * W_DIM + w]);
            if (tr.x < MASK_P) m.x = 0.f;
            if (tr.y < MASK_P) m.y = 0.f;
            if (tr.z < MASK_P) m.z = 0.f;
            if (tr.w < MASK_P) m.w = 0.f;
        }
        int lf = w - s_fs[b];
        if ((unsigned)lf < (unsigned)MASK_LEN) {
            float4 fr = __ldg(&freq_rand[(b * H_DIM + h) * MASK_LEN + lf]);
            if (fr.x < MASK_P) m.x = 0.f;
            if (fr.y < MASK_P) m.y = 0.f;
            if (fr.z < MASK_P) m.z = 0.f;
            if (fr.w < MASK_P) m.w = 0.f;
        }
    }

    // ---- Phase 2: stream this chunk's batches through the pixel ----
    const int pix = h * W_DIM + w;           // index in float4 units
    const int HW  = H_DIM * W_DIM;
    const int b0  = blockIdx.y * B_PER_T;

    const float4* __restrict__ xp = x   + (size_t)b0 * HW + pix;
    float4*       __restrict__ op = out + (size_t)b0 * HW + pix;

    #pragma unroll
    for (int b = 0; b < B_PER_T; ++b) {
        float4 v = xp[b * HW];
        v.x *= m.x; v.y *= m.y; v.z *= m.z; v.w *= m.w;
        op[b * HW] = v;
    }
}

extern "C" void kernel_launch(void* const* d_in, const int* in_sizes, int n_in,
                              void* d_out, int out_size)
{
    const float4* x    = (const float4*)d_in[0];
    const float4* tr   = (const float4*)d_in[1];
    const float4* fr   = (const float4*)d_in[2];
    const int*    ts   = (const int*)d_in[3];
    const int*    fs   = (const int*)d_in[4];
    float4*       out  = (float4*)d_out;

    const int pixels = H_DIM * W_DIM;        // 131072 pixel-threads
    dim3 block(256);
    dim3 grid(pixels / 256, BSPLIT);         // 512 x 4 = 2048 blocks
    masking_kernel<<<grid, block>>>(x, tr, fr, ts, fs, out);
}

// round 3
// speedup vs baseline: 1.0429x; 1.0429x over previous
#include <cuda_runtime.h>

// Problem constants (match reference)
#define MASK_P   0.15f
#define MASK_LEN 8
#define B_DIM    64
#define H_DIM    512
#define W_DIM    256
#define C_DIM    4
#define HW       (H_DIM * W_DIM)       // 131072 pixels (each = one float4)

#define BSPLIT   4                     // batch chunks for stream kernel
#define B_PER_T  (B_DIM / BSPLIT)      // 16 batches streamed per thread

// Scratch: precomputed mask, one float4 (C=4 channels) per (h,w) pixel.
__device__ float4 g_mask[HW];

// ---------------------------------------------------------------------------
// Kernel 1: build mask[H,W,C]. One thread per pixel. Tiny (~8 MiB traffic).
// ---------------------------------------------------------------------------
__global__ __launch_bounds__(256)
void mask_kernel(const float4* __restrict__ time_rand,   // [B,8,W] of float4
                 const float4* __restrict__ freq_rand,   // [B,H,8] of float4
                 const int*    __restrict__ time_starts,
                 const int*    __restrict__ freq_starts)
{
    __shared__ int s_ts[B_DIM];
    __shared__ int s_fs[B_DIM];
    if (threadIdx.x < B_DIM) {
        s_ts[threadIdx.x] = time_starts[threadIdx.x];
        s_fs[threadIdx.x] = freq_starts[threadIdx.x];
    }
    __syncthreads();

    const int tid = blockIdx.x * blockDim.x + threadIdx.x;   // pixel id
    const int w = tid & (W_DIM - 1);
    const int h = tid >> 8;

    float4 m = make_float4(1.f, 1.f, 1.f, 1.f);

    #pragma unroll 4
    for (int b = 0; b < B_DIM; ++b) {
        int lt = h - s_ts[b];
        if ((unsigned)lt < (unsigned)MASK_LEN) {
            float4 tr = __ldg(&time_rand[(b * MASK_LEN + lt) * W_DIM + w]);
            if (tr.x < MASK_P) m.x = 0.f;
            if (tr.y < MASK_P) m.y = 0.f;
            if (tr.z < MASK_P) m.z = 0.f;
            if (tr.w < MASK_P) m.w = 0.f;
        }
        int lf = w - s_fs[b];
        if ((unsigned)lf < (unsigned)MASK_LEN) {
            float4 fr = __ldg(&freq_rand[(b * H_DIM + h) * MASK_LEN + lf]);
            if (fr.x < MASK_P) m.x = 0.f;
            if (fr.y < MASK_P) m.y = 0.f;
            if (fr.z < MASK_P) m.z = 0.f;
            if (fr.w < MASK_P) m.w = 0.f;
        }
    }

    g_mask[tid] = m;
}

// ---------------------------------------------------------------------------
// Kernel 2: pure streaming multiply. Prologue = ONE L2-resident mask load,
// then 16 unrolled float4 load/mul/store iterations (front-batched -> MLP).
// ---------------------------------------------------------------------------
__global__ __launch_bounds__(256)
void stream_kernel(const float4* __restrict__ x,
                   float4*       __restrict__ out)
{
    const int pix = blockIdx.x * blockDim.x + threadIdx.x;   // pixel id
    const int b0  = blockIdx.y * B_PER_T;

    const float4 m = g_mask[pix];       // 2 MiB table: L2 hit after kernel 1

    const float4* __restrict__ xp = x   + (size_t)b0 * HW + pix;
    float4*       __restrict__ op = out + (size_t)b0 * HW + pix;

    #pragma unroll
    for (int b = 0; b < B_PER_T; ++b) {
        float4 v = xp[b * HW];
        v.x *= m.x; v.y *= m.y; v.z *= m.z; v.w *= m.w;
        op[b * HW] = v;
    }
}

extern "C" void kernel_launch(void* const* d_in, const int* in_sizes, int n_in,
                              void* d_out, int out_size)
{
    const float4* x    = (const float4*)d_in[0];
    const float4* tr   = (const float4*)d_in[1];
    const float4* fr   = (const float4*)d_in[2];
    const int*    ts   = (const int*)d_in[3];
    const int*    fs   = (const int*)d_in[4];
    float4*       out  = (float4*)d_out;

    dim3 block(256);
    dim3 grid1(HW / 256);                 // 512 blocks
    mask_kernel<<<grid1, block>>>(tr, fr, ts, fs);

    dim3 grid2(HW / 256, BSPLIT);         // 512 x 4 = 2048 blocks
    stream_kernel<<<grid2, block>>>(x, out);
}

// round 4
// speedup vs baseline: 1.0740x; 1.0298x over previous
#include <cuda_runtime.h>

// Problem constants (match reference)
#define MASK_P   0.15f
#define MASK_LEN 8
#define B_DIM    64
#define H_DIM    512
#define W_DIM    256
#define HW       (H_DIM * W_DIM)       // 131072 pixels (each = one float4)

#define BSPLIT   4                     // batch chunks for stream kernel
#define B_PER_T  (B_DIM / BSPLIT)      // 16 batches streamed per thread

// Scratch: precomputed mask, one float4 (C=4 channels) per (h,w) pixel.
__device__ float4 g_mask[HW];

__device__ __forceinline__ void apply(float4& m, float4 r) {
    if (r.x < MASK_P) m.x = 0.f;
    if (r.y < MASK_P) m.y = 0.f;
    if (r.z < MASK_P) m.z = 0.f;
    if (r.w < MASK_P) m.w = 0.f;
}

// ---------------------------------------------------------------------------
// Kernel 1: build mask[H,W,C]. Block = one h row. Batch scans are replaced by
// ballot-compacted active/candidate bitmasks, so the loop body runs only for
// batches that can actually touch this row/warp (~1 time + ~10 freq of 64).
// ---------------------------------------------------------------------------
__global__ __launch_bounds__(256)
void mask_kernel(const float4* __restrict__ time_rand,   // [B,8,W] of float4
                 const float4* __restrict__ freq_rand,   // [B,H,8] of float4
                 const int*    __restrict__ time_starts,
                 const int*    __restrict__ freq_starts)
{
    const int h = blockIdx.x;          // 512 blocks, one per row
    const int w = threadIdx.x;         // 256 threads, one per column

    __shared__ int s_ts[B_DIM];
    __shared__ int s_fs[B_DIM];
    __shared__ unsigned s_tact[2];     // 64-bit time-active batch mask

    if (w < B_DIM) {
        s_ts[w] = time_starts[w];
        s_fs[w] = freq_starts[w];
    }
    __syncthreads();

    const int warp = w >> 5;
    const int lane = w & 31;

    // Time-active batches for this row (h uniform across block): 2 ballots.
    if (warp < 2) {
        int b = warp * 32 + lane;
        unsigned flag = ((unsigned)(h - s_ts[b]) < (unsigned)MASK_LEN) ? 1u : 0u;
        unsigned bal = __ballot_sync(0xFFFFFFFFu, flag);
        if (lane == 0) s_tact[warp] = bal;
    }
    __syncthreads();

    float4 m = make_float4(1.f, 1.f, 1.f, 1.f);

    // ---- time contributions: iterate only active bits (uniform control) ----
    #pragma unroll
    for (int half = 0; half < 2; ++half) {
        unsigned act = s_tact[half];
        while (act) {
            int b = half * 32 + (__ffs(act) - 1);
            act &= act - 1;
            int lt = h - s_ts[b];                       // guaranteed in [0,8)
            float4 tr = __ldg(&time_rand[(b * MASK_LEN + lt) * W_DIM + w]);
            apply(m, tr);
        }
    }

    // ---- freq candidates: batch b can touch this warp iff
    //      fs[b] in [w0-7, w0+31]  (w0 = warp's base column) ----
    const int w0 = w & ~31;
    unsigned f0 = ((unsigned)(s_fs[lane]      - w0 + (MASK_LEN - 1)) < (unsigned)(32 + MASK_LEN - 1)) ? 1u : 0u;
    unsigned f1 = ((unsigned)(s_fs[lane + 32] - w0 + (MASK_LEN - 1)) < (unsigned)(32 + MASK_LEN - 1)) ? 1u : 0u;
    unsigned c0 = __ballot_sync(0xFFFFFFFFu, f0);
    unsigned c1 = __ballot_sync(0xFFFFFFFFu, f1);

    while (c0) {
        int b = __ffs(c0) - 1;
        c0 &= c0 - 1;
        int lf = w - s_fs[b];
        if ((unsigned)lf < (unsigned)MASK_LEN) {        // short arm -> predicated
            float4 fr = __ldg(&freq_rand[(b * H_DIM + h) * MASK_LEN + lf]);
            apply(m, fr);
        }
    }
    while (c1) {
        int b = 32 + (__ffs(c1) - 1);
        c1 &= c1 - 1;
        int lf = w - s_fs[b];
        if ((unsigned)lf < (unsigned)MASK_LEN) {
            float4 fr = __ldg(&freq_rand[(b * H_DIM + h) * MASK_LEN + lf]);
            apply(m, fr);
        }
    }

    g_mask[h * W_DIM + w] = m;
}

// ---------------------------------------------------------------------------
// Kernel 2: pure streaming multiply (unchanged from R3 — measured 38.1us,
// DRAM 72.5%, occ 81%).
// ---------------------------------------------------------------------------
__global__ __launch_bounds__(256)
void stream_kernel(const float4* __restrict__ x,
                   float4*       __restrict__ out)
{
    const int pix = blockIdx.x * blockDim.x + threadIdx.x;   // pixel id
    const int b0  = blockIdx.y * B_PER_T;

    const float4 m = g_mask[pix];       // 2 MiB table: L2 hit after kernel 1

    const float4* __restrict__ xp = x   + (size_t)b0 * HW + pix;
    float4*       __restrict__ op = out + (size_t)b0 * HW + pix;

    #pragma unroll
    for (int b = 0; b < B_PER_T; ++b) {
        float4 v = xp[b * HW];
        v.x *= m.x; v.y *= m.y; v.z *= m.z; v.w *= m.w;
        op[b * HW] = v;
    }
}

extern "C" void kernel_launch(void* const* d_in, const int* in_sizes, int n_in,
                              void* d_out, int out_size)
{
    const float4* x    = (const float4*)d_in[0];
    const float4* tr   = (const float4*)d_in[1];
    const float4* fr   = (const float4*)d_in[2];
    const int*    ts   = (const int*)d_in[3];
    const int*    fs   = (const int*)d_in[4];
    float4*       out  = (float4*)d_out;

    dim3 block(256);
    mask_kernel<<<H_DIM, block>>>(tr, fr, ts, fs);           // 512 blocks

    dim3 grid2(HW / 256, BSPLIT);                            // 512 x 4
    stream_kernel<<<grid2, block>>>(x, out);
}